// round 5
// baseline (speedup 1.0000x reference)
#include <cuda_runtime.h>
#include <cuda_fp16.h>
#include <cstdint>

#define BATCH 2
#define HEADS 16
#define SEQ   4096
#define DIM   64
#define WIN   512
#define HALF  256
#define NFULL 15
#define P0    3840
#define ROWS_PER_BH 7936
#define BH    (BATCH*HEADS)

__device__ float g_ws[(size_t)BH * ROWS_PER_BH * DIM];   // per-window outputs

#define KSTRIDE 72            // halves per smem row (64 data + 8 pad)
#define ROWB    (KSTRIDE*2)   // 144 bytes

__device__ __forceinline__ uint32_t pack_h2(float a, float b) {
    __half2 h = __floats2half2_rn(a, b);
    return *(uint32_t*)&h;
}
__device__ __forceinline__ float sigmoid_fast(float x) {
    float t;
    asm("tanh.approx.f32 %0, %1;" : "=f"(t) : "f"(x * 0.5f));
    return fmaf(t, 0.5f, 0.5f);
}
__device__ __forceinline__ void mma_f16(float c[4], const uint32_t a[4], uint32_t b0, uint32_t b1) {
    asm volatile(
        "mma.sync.aligned.m16n8k16.row.col.f32.f16.f16.f32 "
        "{%0,%1,%2,%3}, {%4,%5,%6,%7}, {%8,%9}, {%0,%1,%2,%3};"
        : "+f"(c[0]), "+f"(c[1]), "+f"(c[2]), "+f"(c[3])
        : "r"(a[0]), "r"(a[1]), "r"(a[2]), "r"(a[3]), "r"(b0), "r"(b1));
}
__device__ __forceinline__ void ldsm_x4(uint32_t r[4], uint32_t addr) {
    asm volatile("ldmatrix.sync.aligned.m8n8.x4.shared.b16 {%0,%1,%2,%3}, [%4];"
                 : "=r"(r[0]), "=r"(r[1]), "=r"(r[2]), "=r"(r[3]) : "r"(addr));
}
__device__ __forceinline__ void ldsm_x4_t(uint32_t r[4], uint32_t addr) {
    asm volatile("ldmatrix.sync.aligned.m8n8.x4.trans.shared.b16 {%0,%1,%2,%3}, [%4];"
                 : "=r"(r[0]), "=r"(r[1]), "=r"(r[2]), "=r"(r[3]) : "r"(addr));
}
__device__ __forceinline__ uint32_t smem_u32(const void* p) {
    uint32_t a;
    asm("{ .reg .u64 t; cvta.to.shared.u64 t, %1; cvt.u32.u64 %0, t; }" : "=r"(a) : "l"(p));
    return a;
}

__global__ __launch_bounds__(256, 2)
void win_attn_h(const float* __restrict__ Q,
                const float* __restrict__ K,
                const float* __restrict__ V,
                const float* __restrict__ scale_p)
{
    __shared__ __align__(16) __half smK[64 * KSTRIDE];  // [key][dim] fp16
    __shared__ __align__(16) __half smV[64 * KSTRIDE];  // [key][dim] fp16

    const int tid  = threadIdx.x;
    const int lane = tid & 31;
    const int warp = tid >> 5;
    const int gid  = lane >> 2;
    const int tig  = lane & 3;

    const int bh = blockIdx.y;
    const int t  = blockIdx.x;

    int nkeys, key_start, row0, qoff;
    if (t < 60) {
        int w = t >> 2, qt = t & 3;
        nkeys = WIN; key_start = w * HALF; row0 = w * WIN + qt * 128; qoff = qt * 128;
    } else {
        int qt = t - 60;
        nkeys = HALF; key_start = P0; row0 = NFULL * WIN + qt * 128; qoff = qt * 128;
    }
    const int nchunks = nkeys >> 6;
    const size_t base = (size_t)bh * SEQ * DIM;
    const float scale = *scale_p;

    // ---- Q fragments (m16n8k16 A), fp16, scale folded in ----
    uint32_t qa[4][4];
    {
        const float* q0 = Q + base + (size_t)(key_start + qoff + warp * 16 + gid) * DIM;
        const float* q1 = q0 + 8 * DIM;
        #pragma unroll
        for (int ks = 0; ks < 4; ks++) {
            float2 v;
            v = *(const float2*)(q0 + ks * 16 + 2 * tig);
            qa[ks][0] = pack_h2(v.x * scale, v.y * scale);
            v = *(const float2*)(q1 + ks * 16 + 2 * tig);
            qa[ks][1] = pack_h2(v.x * scale, v.y * scale);
            v = *(const float2*)(q0 + ks * 16 + 2 * tig + 8);
            qa[ks][2] = pack_h2(v.x * scale, v.y * scale);
            v = *(const float2*)(q1 + ks * 16 + 2 * tig + 8);
            qa[ks][3] = pack_h2(v.x * scale, v.y * scale);
        }
    }

    float dacc[8][4];
    #pragma unroll
    for (int nt = 0; nt < 8; nt++)
        #pragma unroll
        for (int i = 0; i < 4; i++) dacc[nt][i] = 0.0f;
    float den0 = 0.0f, den1 = 0.0f;

    // ldmatrix base addresses (chunk-invariant)
    // MMA1 (K, non-trans): matrices m=0..3 -> dim-blocks; rows = keys (per nt add nt*8*ROWB)
    const uint32_t kA = smem_u32(smK) + (uint32_t)(lane & 7) * ROWB + (uint32_t)(lane >> 3) * 16;
    // MMA2 (V, trans): matrices m=0..3 -> key-blocks; cols = dims (per nt add nt*16)
    const uint32_t vA = smem_u32(smV) + (uint32_t)(((lane >> 3) * 8 + (lane & 7))) * ROWB;

    // prefetch chunk 0
    float4 kreg[4], vreg[4];
    {
        const float4* kg = (const float4*)(K + base + (size_t)key_start * DIM);
        const float4* vg = (const float4*)(V + base + (size_t)key_start * DIM);
        #pragma unroll
        for (int i = 0; i < 4; i++) { kreg[i] = kg[tid + i * 256]; vreg[i] = vg[tid + i * 256]; }
    }

    for (int c = 0; c < nchunks; c++) {
        if (c > 0) __syncthreads();
        // ---- store staged K/V (fp16, [key][dim], vectorized) ----
        #pragma unroll
        for (int i = 0; i < 4; i++) {
            int idx = tid + i * 256;
            int r = idx >> 4, c4 = idx & 15;
            uint2 kk = { pack_h2(kreg[i].x, kreg[i].y), pack_h2(kreg[i].z, kreg[i].w) };
            uint2 vv = { pack_h2(vreg[i].x, vreg[i].y), pack_h2(vreg[i].z, vreg[i].w) };
            *(uint2*)((char*)smK + r * ROWB + c4 * 8) = kk;
            *(uint2*)((char*)smV + r * ROWB + c4 * 8) = vv;
        }
        __syncthreads();

        // prefetch next chunk (overlaps the MMAs below)
        if (c + 1 < nchunks) {
            const int k1 = key_start + (c + 1) * 64;
            const float4* kg = (const float4*)(K + base + (size_t)k1 * DIM);
            const float4* vg = (const float4*)(V + base + (size_t)k1 * DIM);
            #pragma unroll
            for (int i = 0; i < 4; i++) { kreg[i] = kg[tid + i * 256]; vreg[i] = vg[tid + i * 256]; }
        }

        // ---- MMA1 per n-tile + sigmoid -> register-resident P fragments ----
        uint32_t pa[4][4];
        #pragma unroll
        for (int nt = 0; nt < 8; nt++) {
            uint32_t kb[8];
            const uint32_t ka = kA + (uint32_t)nt * (8 * ROWB);
            ldsm_x4(kb + 0, ka);        // dim-blocks 0..3 -> ks 0,1
            ldsm_x4(kb + 4, ka + 64);   // dim-blocks 4..7 -> ks 2,3
            float sl[4] = {0.0f, 0.0f, 0.0f, 0.0f};
            #pragma unroll
            for (int ks = 0; ks < 4; ks++)
                mma_f16(sl, qa[ks], kb[2 * ks], kb[2 * ks + 1]);

            float p0 = sigmoid_fast(sl[0]);
            float p1 = sigmoid_fast(sl[1]);
            float p2 = sigmoid_fast(sl[2]);
            float p3 = sigmoid_fast(sl[3]);
            uint32_t u01 = pack_h2(p0, p1);
            uint32_t u23 = pack_h2(p2, p3);
            float2 f01 = __half22float2(*(__half2*)&u01);
            float2 f23 = __half22float2(*(__half2*)&u23);
            den0 += f01.x + f01.y;
            den1 += f23.x + f23.y;
            int kc = nt >> 1, hi = (nt & 1) * 2;
            pa[kc][hi]     = u01;
            pa[kc][hi + 1] = u23;
        }

        // ---- MMA2: D += P . V  (B via ldmatrix.trans on row-major V) ----
        #pragma unroll
        for (int nt = 0; nt < 8; nt++) {
            uint32_t vb[8];
            const uint32_t va = vA + (uint32_t)nt * 16;
            ldsm_x4_t(vb + 0, va);          // key-blocks 0..3 -> kc 0,1
            ldsm_x4_t(vb + 4, va + 4608);   // key-blocks 4..7 -> kc 2,3  (4*8*ROWB)
            #pragma unroll
            for (int kc = 0; kc < 4; kc++)
                mma_f16(dacc[nt], pa[kc], vb[2 * kc], vb[2 * kc + 1]);
        }
    }

    // ---- denom reduce within quad ----
    den0 += __shfl_xor_sync(0xFFFFFFFF, den0, 1);
    den0 += __shfl_xor_sync(0xFFFFFFFF, den0, 2);
    den1 += __shfl_xor_sync(0xFFFFFFFF, den1, 1);
    den1 += __shfl_xor_sync(0xFFFFFFFF, den1, 2);
    const float inv0 = 1.0f / den0;
    const float inv1 = 1.0f / den1;

    // ---- epilogue: D/denom -> g_ws ----
    {
        float* o0 = g_ws + ((size_t)bh * ROWS_PER_BH + row0 + warp * 16 + gid) * DIM;
        float* o1 = o0 + 8 * DIM;
        #pragma unroll
        for (int nt = 0; nt < 8; nt++) {
            float2 r0 = { dacc[nt][0] * inv0, dacc[nt][1] * inv0 };
            float2 r1 = { dacc[nt][2] * inv1, dacc[nt][3] * inv1 };
            *(float2*)(o0 + nt * 8 + 2 * tig) = r0;
            *(float2*)(o1 + nt * 8 + 2 * tig) = r1;
        }
    }
}

// ---------------- Blend ----------------
__global__ __launch_bounds__(256)
void blend_kernel(float* __restrict__ out)
{
    const int D4 = DIM / 4;
    size_t tid = (size_t)blockIdx.x * blockDim.x + threadIdx.x;
    const size_t total = (size_t)BH * SEQ * D4;
    if (tid >= total) return;

    int d4 = (int)(tid % D4);
    size_t r = tid / D4;
    int s  = (int)(r % SEQ);
    int bh = (int)(r / SEQ);

    int k = s >> 8;
    int i = s & 255;
    float a = (float)i * (1.0f / 255.0f);

    const float4* ws = (const float4*)(g_ws + (size_t)bh * ROWS_PER_BH * DIM);

    float4 res;
    if (k == 0) {
        res = ws[(size_t)i * D4 + d4];
    } else if (k < NFULL) {
        float4 v0 = ws[(size_t)((k - 1) * WIN + HALF + i) * D4 + d4];
        float4 v1 = ws[(size_t)(k * WIN + i) * D4 + d4];
        res.x = (1.0f - a) * v0.x + a * v1.x;
        res.y = (1.0f - a) * v0.y + a * v1.y;
        res.z = (1.0f - a) * v0.z + a * v1.z;
        res.w = (1.0f - a) * v0.w + a * v1.w;
    } else {
        float4 v0 = ws[(size_t)((NFULL - 1) * WIN + HALF + i) * D4 + d4];
        float4 v1 = ws[(size_t)(NFULL * WIN + i) * D4 + d4];
        res.x = (1.0f - a) * v0.x + a * v1.x;
        res.y = (1.0f - a) * v0.y + a * v1.y;
        res.z = (1.0f - a) * v0.z + a * v1.z;
        res.w = (1.0f - a) * v0.w + a * v1.w;
    }
    ((float4*)out)[tid] = res;
}

extern "C" void kernel_launch(void* const* d_in, const int* in_sizes, int n_in,
                              void* d_out, int out_size)
{
    const float* Q     = (const float*)d_in[0];
    const float* K     = (const float*)d_in[1];
    const float* V     = (const float*)d_in[2];
    const float* scale = (const float*)d_in[3];
    float* out = (float*)d_out;

    dim3 grid(62, BH);
    win_attn_h<<<grid, 256>>>(Q, K, V, scale);

    const size_t total4 = (size_t)BH * SEQ * (DIM / 4);
    int blocks = (int)((total4 + 255) / 256);
    blend_kernel<<<blocks, 256>>>(out);
}